// round 15
// baseline (speedup 1.0000x reference)
#include <cuda_runtime.h>
#include <cstdint>
#include <cstddef>

// out = (G @ W @ A) @ depthwise_conv3x3(x)
// x: [8, 64, 256, 256] f32; out same shape.

#define NCH 64
#define IMG 256
#define TW 128
#define TH 2
#define NCTA 444           // persistent grid: 148 SMs x 3 CTAs
#define NTILE 2048         // 8 batches x 128 row-tiles x 2 col-tiles
#define DWS_S 264          // row stride (floats); 264 % 32 == 8 -> conflict-free B frags
#define SMEM_BYTES (NCH * DWS_S * 4)   // 67584 B -> 3 CTAs/SM

__device__ float g_Mp[8 * 4 * NCH * 2];   // M packed as [ks][m][row][2] tf32 fragments
__constant__ float c_dw[NCH * 9];         // depthwise weights (const cache)

// ---------------------------------------------------------------------------
__device__ __forceinline__ unsigned f2tf(float x) {
    unsigned r;
    asm("cvt.rna.tf32.f32 %0, %1;" : "=r"(r) : "f"(x));
    return r;
}

__device__ __forceinline__ float2 ldg_v2(const float2* p) {
    float2 r;   // opaque load: keeps A-fragments out of long-lived registers
    asm volatile("ld.global.nc.v2.f32 {%0,%1}, [%2];"
                 : "=f"(r.x), "=f"(r.y) : "l"(p));
    return r;
}

__device__ __forceinline__ void mma_tf32(float d[4], const unsigned* a,
                                         unsigned b0, unsigned b1) {
    asm volatile(
        "mma.sync.aligned.m16n8k8.row.col.f32.tf32.tf32.f32 "
        "{%0,%1,%2,%3}, {%4,%5,%6,%7}, {%8,%9}, {%0,%1,%2,%3};\n"
        : "+f"(d[0]), "+f"(d[1]), "+f"(d[2]), "+f"(d[3])
        : "r"(a[0]), "r"(a[1]), "r"(a[2]), "r"(a[3]), "r"(b0), "r"(b1));
}

// ---------------------------------------------------------------------------
// Kernel 1: M = softmax(G) @ W @ softmax(A), packed to fragment order.
// ONE launch, grid 16 x 256.  CTA owns 4 output rows; softmaxes its own 4
// G-rows (row-local) and redundantly computes full softmax(A) in smem.
// ---------------------------------------------------------------------------
__global__ void kMall(const float* __restrict__ aw, const float* __restrict__ gw,
                      const float* __restrict__ pw) {
    __shared__ float As[NCH * NCH];
    __shared__ float sw[NCH * NCH];
    __shared__ float sg[4 * NCH];
    __shared__ float sp[4 * NCH];
    __shared__ float red[8];

    const int t = threadIdx.x;
    const int rr = t >> 6, c = t & 63;   // local row 0..3, column 0..63
    const int i = blockIdx.x * 4 + rr;   // global output row

    // ---- softmax of the CTA's 4 G rows -> sg ----
    float v = __ldg(gw + i * NCH + c);
    float mx = v;
    #pragma unroll
    for (int o = 16; o > 0; o >>= 1) mx = fmaxf(mx, __shfl_xor_sync(~0u, mx, o));
    if ((t & 31) == 0) red[t >> 5] = mx;
    __syncthreads();
    mx = fmaxf(red[rr * 2], red[rr * 2 + 1]);
    __syncthreads();
    float e = __expf(v - mx);
    float sum = e;
    #pragma unroll
    for (int o = 16; o > 0; o >>= 1) sum += __shfl_xor_sync(~0u, sum, o);
    if ((t & 31) == 0) red[t >> 5] = sum;
    // stage W while the reduction settles
    for (int idx = t; idx < NCH * NCH; idx += 256) sw[idx] = __ldg(pw + idx);
    __syncthreads();
    sum = red[rr * 2] + red[rr * 2 + 1];
    sg[rr * NCH + c] = e / sum;

    // ---- full softmax(A) -> As (4 threads per row, shfl within quad) ----
    {
        const int r = t >> 2, s = t & 3;
        const float* row = aw + r * NCH;
        float m2 = -3.4e38f;
        for (int j = s; j < NCH; j += 4) m2 = fmaxf(m2, __ldg(row + j));
        m2 = fmaxf(m2, __shfl_xor_sync(~0u, m2, 1));
        m2 = fmaxf(m2, __shfl_xor_sync(~0u, m2, 2));
        float s2 = 0.f;
        for (int j = s; j < NCH; j += 4) {
            float ee = __expf(__ldg(row + j) - m2);
            As[r * NCH + j] = ee;
            s2 += ee;
        }
        s2 += __shfl_xor_sync(~0u, s2, 1);
        s2 += __shfl_xor_sync(~0u, s2, 2);
        float inv = 1.f / s2;
        for (int j = s; j < NCH; j += 4) As[r * NCH + j] *= inv;
    }
    __syncthreads();

    // ---- sp = sg @ W ----
    {
        float acc = 0.f;
        #pragma unroll 8
        for (int j = 0; j < NCH; j++)
            acc = fmaf(sg[rr * NCH + j], sw[j * NCH + c], acc);
        sp[rr * NCH + c] = acc;
    }
    __syncthreads();

    // ---- M row = sp @ As, packed ----
    {
        float acc = 0.f;
        #pragma unroll 8
        for (int j = 0; j < NCH; j++)
            acc = fmaf(sp[rr * NCH + j], As[j * NCH + c], acc);
        const int ks = c >> 3, w = c & 7, mm = w & 3, h = w >> 2;
        g_Mp[(((ks * 4 + mm) * NCH) + i) * 2 + h] = __uint_as_float(f2tf(acc));
    }
}

// ---------------------------------------------------------------------------
// Kernel 2: fused depthwise-conv + channel mix, PERSISTENT grid (444 CTAs,
//   3 CTAs/SM).  A-fragments streamed from L2-hot g_Mp per ks-step so the
//   register budget fits 3 CTAs/SM (launch_bounds enforces <=85 regs).
// ---------------------------------------------------------------------------
__global__ void __launch_bounds__(256, 3)
fused_kernel(const float* __restrict__ x, float* __restrict__ out) {
    extern __shared__ float dws[];   // [64 ch][256 px] stride 264

    const int t    = threadIdx.x;
    const int lane = t & 31;
    const int wid  = t >> 5;

    const int warpM = wid & 1;       // 2 groups of 32 out-channels
    const int warpN = wid >> 1;      // 4 groups of 64 pixels
    const int g = lane >> 2, m = lane & 3;
    const int r0 = warpM * 32 + g;
    const int cBase = wid * 8;
    const float2* MpBase = (const float2*)g_Mp;

    bool first = true;

    #pragma unroll 1
    for (int tid = blockIdx.x; tid < NTILE; tid += NCTA) {
        // tile -> (batch, row-tile, col-tile)
        const int b  = tid >> 8;
        const int y0 = ((tid >> 1) & 127) * TH;
        const int x0 = (tid & 1) * TW;
        const float* xbase = x + (((size_t)(b * NCH + cBase)) << 16);

        if (!first) __syncthreads();   // previous MMA reads of dws complete
        first = false;

        // ------------------ depthwise 3x3 conv, warp-per-8-channels --------
        {
            const int ecol = (lane < 4) ? (x0 - 1) : (x0 + TW);
            const int erow = y0 - 1 + (lane & 3);
            const bool eok = (lane < 8) && ((unsigned)ecol < (unsigned)IMG) &&
                             ((unsigned)erow < (unsigned)IMG);

            #pragma unroll 2
            for (int i = 0; i < 8; i++) {
                const int c = cBase + i;
                const float* xc = xbase + ((size_t)i << 16);

                float4 v[4];
                #pragma unroll
                for (int k = 0; k < 4; k++) {
                    const int yk = y0 - 1 + k;
                    v[k] = ((unsigned)yk < (unsigned)IMG)
                         ? __ldg((const float4*)(xc + yk * IMG + x0) + lane)
                         : make_float4(0.f, 0.f, 0.f, 0.f);
                }
                const float e = eok ? __ldg(xc + erow * IMG + ecol) : 0.f;

                float4 ot = make_float4(0.f, 0.f, 0.f, 0.f);
                float4 ob = make_float4(0.f, 0.f, 0.f, 0.f);
                #pragma unroll
                for (int k = 0; k < 4; k++) {
                    float fL = __shfl_up_sync(0xffffffffu, v[k].w, 1);
                    const float eL = __shfl_sync(0xffffffffu, e, k);
                    if (lane == 0) fL = eL;
                    float fR = __shfl_down_sync(0xffffffffu, v[k].x, 1);
                    const float eR = __shfl_sync(0xffffffffu, e, 4 + k);
                    if (lane == 31) fR = eR;
                    if (k <= 2) {   // weight row k -> top output row
                        const float wa = c_dw[c * 9 + 3 * k];
                        const float wb = c_dw[c * 9 + 3 * k + 1];
                        const float wc = c_dw[c * 9 + 3 * k + 2];
                        ot.x = fmaf(wa, fL,     fmaf(wb, v[k].x, fmaf(wc, v[k].y, ot.x)));
                        ot.y = fmaf(wa, v[k].x, fmaf(wb, v[k].y, fmaf(wc, v[k].z, ot.y)));
                        ot.z = fmaf(wa, v[k].y, fmaf(wb, v[k].z, fmaf(wc, v[k].w, ot.z)));
                        ot.w = fmaf(wa, v[k].z, fmaf(wb, v[k].w, fmaf(wc, fR,     ot.w)));
                    }
                    if (k >= 1) {   // weight row k-1 -> bottom output row
                        const float wa = c_dw[c * 9 + 3 * (k - 1)];
                        const float wb = c_dw[c * 9 + 3 * (k - 1) + 1];
                        const float wc = c_dw[c * 9 + 3 * (k - 1) + 2];
                        ob.x = fmaf(wa, fL,     fmaf(wb, v[k].x, fmaf(wc, v[k].y, ob.x)));
                        ob.y = fmaf(wa, v[k].x, fmaf(wb, v[k].y, fmaf(wc, v[k].z, ob.y)));
                        ob.z = fmaf(wa, v[k].y, fmaf(wb, v[k].z, fmaf(wc, v[k].w, ob.z)));
                        ob.w = fmaf(wa, v[k].z, fmaf(wb, v[k].w, fmaf(wc, fR,     ob.w)));
                    }
                }
                float4 st;
                st.x = __uint_as_float(f2tf(ot.x));
                st.y = __uint_as_float(f2tf(ot.y));
                st.z = __uint_as_float(f2tf(ot.z));
                st.w = __uint_as_float(f2tf(ot.w));
                *reinterpret_cast<float4*>(dws + c * DWS_S + 4 * lane) = st;
                st.x = __uint_as_float(f2tf(ob.x));
                st.y = __uint_as_float(f2tf(ob.y));
                st.z = __uint_as_float(f2tf(ob.z));
                st.w = __uint_as_float(f2tf(ob.w));
                *reinterpret_cast<float4*>(dws + c * DWS_S + TW + 4 * lane) = st;
            }
        }

        __syncthreads();   // dws ready

        // ---- channel mix: out[64,256] = M @ dw  via m16n8k8 tf32 MMA ----
        // A-fragments streamed from L2-hot g_Mp (4KB) each ks-step.
        #pragma unroll 1
        for (int grp = 0; grp < 2; grp++) {
            float acc[2][4][4] = {};
            #pragma unroll
            for (int ks = 0; ks < 8; ks++) {
                const float2* pk = MpBase + (ks * 4 + m) * NCH;
                float2 a0 = ldg_v2(pk + r0);
                float2 a1 = ldg_v2(pk + r0 + 8);
                float2 a2 = ldg_v2(pk + r0 + 16);
                float2 a3 = ldg_v2(pk + r0 + 24);
                unsigned af0[4] = {__float_as_uint(a0.x), __float_as_uint(a1.x),
                                   __float_as_uint(a0.y), __float_as_uint(a1.y)};
                unsigned af1[4] = {__float_as_uint(a2.x), __float_as_uint(a3.x),
                                   __float_as_uint(a2.y), __float_as_uint(a3.y)};
                const float* bp = dws + (ks * 8 + m) * DWS_S;
                #pragma unroll
                for (int pp = 0; pp < 2; pp++) {
                    const int pb0 = warpN * 64 + (grp * 2 + pp) * 16;
                    unsigned b0a = __float_as_uint(bp[pb0 + g]);
                    unsigned b1a = __float_as_uint(bp[4 * DWS_S + pb0 + g]);
                    unsigned b0b = __float_as_uint(bp[pb0 + 8 + g]);
                    unsigned b1b = __float_as_uint(bp[4 * DWS_S + pb0 + 8 + g]);
                    mma_tf32(acc[pp][0], af0, b0a, b1a);
                    mma_tf32(acc[pp][1], af0, b0b, b1b);
                    mma_tf32(acc[pp][2], af1, b0a, b1a);
                    mma_tf32(acc[pp][3], af1, b0b, b1b);
                }
            }
            #pragma unroll
            for (int pp = 0; pp < 2; pp++) {
                const int pb0 = warpN * 64 + (grp * 2 + pp) * 16;
                #pragma unroll
                for (int cc = 0; cc < 2; cc++) {
                    const int p  = pb0 + 8 * cc + 2 * m;
                    const int yy = y0 + (p >> 7);
                    const int xx = x0 + (p & 127);
                    #pragma unroll
                    for (int tt = 0; tt < 2; tt++) {
                        const int och = warpM * 32 + g + 16 * tt;
                        const float* a = acc[pp][2 * tt + cc];
                        size_t o1 = (((size_t)(b * NCH + och)) << 16) + yy * IMG + xx;
                        *reinterpret_cast<float2*>(out + o1) = make_float2(a[0], a[1]);
                        size_t o2 = (((size_t)(b * NCH + och + 8)) << 16) + yy * IMG + xx;
                        *reinterpret_cast<float2*>(out + o2) = make_float2(a[2], a[3]);
                    }
                }
            }
        }
    }
}

// ---------------------------------------------------------------------------
extern "C" void kernel_launch(void* const* d_in, const int* in_sizes, int n_in,
                              void* d_out, int out_size) {
    const float* x   = (const float*)d_in[0];   // [8,64,256,256]
    const float* dww = (const float*)d_in[1];   // [64,1,3,3]
    const float* pww = (const float*)d_in[2];   // [64,64,1,1]
    const float* aw  = (const float*)d_in[3];   // [64,64]
    const float* gw  = (const float*)d_in[4];   // [64,64]
    float* out = (float*)d_out;

    cudaMemcpyToSymbolAsync(c_dw, dww, NCH * 9 * sizeof(float), 0,
                            cudaMemcpyDeviceToDevice);
    kMall<<<16, 256>>>(aw, gw, pww);

    cudaFuncSetAttribute(fused_kernel,
                         cudaFuncAttributeMaxDynamicSharedMemorySize, SMEM_BYTES);
    fused_kernel<<<NCTA, 256, SMEM_BYTES>>>(x, out);
}

// round 16
// speedup vs baseline: 1.4404x; 1.4404x over previous
#include <cuda_runtime.h>
#include <cstdint>
#include <cstddef>

// out = (G @ W @ A) @ depthwise_conv3x3(x)
// x: [8, 64, 256, 256] f32; out same shape.

#define NCH 64
#define IMG 256
#define TW 128
#define TH 4
#define NCTA 148           // persistent grid: 148 SMs x 1 CTA (512 threads)
#define NTILE 1024         // 8 batches x 64 row-tiles x 2 col-tiles
#define DWS_S 520          // row stride (floats); 520 % 32 == 8 -> conflict-free B frags
#define SMEM_BYTES (NCH * DWS_S * 4)   // 133120 B -> 1 CTA/SM

__device__ float g_Mp[8 * 4 * NCH * 2];   // M packed as [ks][m][row][2] tf32 fragments
__constant__ float c_dw[NCH * 9];         // depthwise weights (const cache)

// ---------------------------------------------------------------------------
__device__ __forceinline__ unsigned f2tf(float x) {
    unsigned r;
    asm("cvt.rna.tf32.f32 %0, %1;" : "=r"(r) : "f"(x));
    return r;
}

__device__ __forceinline__ void mma_tf32(float d[4], const unsigned* a,
                                         unsigned b0, unsigned b1) {
    asm volatile(
        "mma.sync.aligned.m16n8k8.row.col.f32.tf32.tf32.f32 "
        "{%0,%1,%2,%3}, {%4,%5,%6,%7}, {%8,%9}, {%0,%1,%2,%3};\n"
        : "+f"(d[0]), "+f"(d[1]), "+f"(d[2]), "+f"(d[3])
        : "r"(a[0]), "r"(a[1]), "r"(a[2]), "r"(a[3]), "r"(b0), "r"(b1));
}

// ---------------------------------------------------------------------------
// Kernel 1: M = softmax(G) @ W @ softmax(A), packed to fragment order.
// ---------------------------------------------------------------------------
__global__ void kMall(const float* __restrict__ aw, const float* __restrict__ gw,
                      const float* __restrict__ pw) {
    __shared__ float As[NCH * NCH];
    __shared__ float sw[NCH * NCH];
    __shared__ float sg[4 * NCH];
    __shared__ float sp[4 * NCH];
    __shared__ float red[8];

    const int t = threadIdx.x;
    const int rr = t >> 6, c = t & 63;   // local row 0..3, column 0..63
    const int i = blockIdx.x * 4 + rr;   // global output row

    // ---- softmax of the CTA's 4 G rows -> sg ----
    float v = __ldg(gw + i * NCH + c);
    float mx = v;
    #pragma unroll
    for (int o = 16; o > 0; o >>= 1) mx = fmaxf(mx, __shfl_xor_sync(~0u, mx, o));
    if ((t & 31) == 0) red[t >> 5] = mx;
    __syncthreads();
    mx = fmaxf(red[rr * 2], red[rr * 2 + 1]);
    __syncthreads();
    float e = __expf(v - mx);
    float sum = e;
    #pragma unroll
    for (int o = 16; o > 0; o >>= 1) sum += __shfl_xor_sync(~0u, sum, o);
    if ((t & 31) == 0) red[t >> 5] = sum;
    for (int idx = t; idx < NCH * NCH; idx += 256) sw[idx] = __ldg(pw + idx);
    __syncthreads();
    sum = red[rr * 2] + red[rr * 2 + 1];
    sg[rr * NCH + c] = e / sum;

    // ---- full softmax(A) -> As (4 threads per row, shfl within quad) ----
    {
        const int r = t >> 2, s = t & 3;
        const float* row = aw + r * NCH;
        float m2 = -3.4e38f;
        for (int j = s; j < NCH; j += 4) m2 = fmaxf(m2, __ldg(row + j));
        m2 = fmaxf(m2, __shfl_xor_sync(~0u, m2, 1));
        m2 = fmaxf(m2, __shfl_xor_sync(~0u, m2, 2));
        float s2 = 0.f;
        for (int j = s; j < NCH; j += 4) {
            float ee = __expf(__ldg(row + j) - m2);
            As[r * NCH + j] = ee;
            s2 += ee;
        }
        s2 += __shfl_xor_sync(~0u, s2, 1);
        s2 += __shfl_xor_sync(~0u, s2, 2);
        float inv = 1.f / s2;
        for (int j = s; j < NCH; j += 4) As[r * NCH + j] *= inv;
    }
    __syncthreads();

    // ---- sp = sg @ W ----
    {
        float acc = 0.f;
        #pragma unroll 8
        for (int j = 0; j < NCH; j++)
            acc = fmaf(sg[rr * NCH + j], sw[j * NCH + c], acc);
        sp[rr * NCH + c] = acc;
    }
    __syncthreads();

    // ---- M row = sp @ As, packed ----
    {
        float acc = 0.f;
        #pragma unroll 8
        for (int j = 0; j < NCH; j++)
            acc = fmaf(sp[rr * NCH + j], As[j * NCH + c], acc);
        const int ks = c >> 3, w = c & 7, mm = w & 3, h = w >> 2;
        g_Mp[(((ks * 4 + mm) * NCH) + i) * 2 + h] = __uint_as_float(f2tf(acc));
    }
}

// ---------------------------------------------------------------------------
// Kernel 2: fused depthwise-conv + channel mix, PERSISTENT 148 CTAs x 512thr.
//   Tile: 4 rows x 128 cols x 64 ch.  Rolling 6-row conv (1.5x read amp).
//   Warp owns 4 channels; A-fragments resident (proven faster than streaming).
// ---------------------------------------------------------------------------
__global__ void __launch_bounds__(512, 1)
fused_kernel(const float* __restrict__ x, float* __restrict__ out) {
    extern __shared__ float dws[];   // [64 ch][512 px] stride 520

    const int t    = threadIdx.x;
    const int lane = t & 31;
    const int wid  = t >> 5;         // 0..15

    const int warpM = wid & 1;       // 2 groups of 32 out-channels
    const int warpN = wid >> 1;      // 8 groups of 64 pixels
    const int g = lane >> 2, m = lane & 3;
    const int r0 = warpM * 32 + g;
    const int cBase = wid * 4;       // 4 channels per warp

    // ---- A fragments: warp owns 32 out-channels (2 m16 tiles), resident ----
    unsigned afr[8][8];
    {
        const float2* Mp = (const float2*)g_Mp;
        #pragma unroll
        for (int ks = 0; ks < 8; ks++) {
            const float2* pk = Mp + (ks * 4 + m) * NCH;
            float2 a0 = __ldg(pk + r0);
            float2 a1 = __ldg(pk + r0 + 8);
            float2 a2 = __ldg(pk + r0 + 16);
            float2 a3 = __ldg(pk + r0 + 24);
            afr[ks][0] = __float_as_uint(a0.x);
            afr[ks][1] = __float_as_uint(a1.x);
            afr[ks][2] = __float_as_uint(a0.y);
            afr[ks][3] = __float_as_uint(a1.y);
            afr[ks][4] = __float_as_uint(a2.x);
            afr[ks][5] = __float_as_uint(a3.x);
            afr[ks][6] = __float_as_uint(a2.y);
            afr[ks][7] = __float_as_uint(a3.y);
        }
    }

    bool first = true;

    #pragma unroll 1
    for (int tid = blockIdx.x; tid < NTILE; tid += NCTA) {
        // tile -> (batch, row-tile, col-tile)
        const int b  = tid >> 7;               // 128 tiles per batch
        const int y0 = ((tid >> 1) & 63) * TH;
        const int x0 = (tid & 1) * TW;
        const float* xbase = x + (((size_t)(b * NCH + cBase)) << 16);

        if (!first) __syncthreads();   // previous MMA reads of dws complete
        first = false;

        // ---- depthwise 3x3 conv: 6 input rows -> 4 output rows, rolling ----
        {
            // edge column values: lanes 0..5 left col rows 0..5, 6..11 right
            const int ecol = (lane < 6) ? (x0 - 1) : (x0 + TW);
            const int erow = y0 - 1 + ((lane < 6) ? lane : lane - 6);
            const bool eok = (lane < 12) && ((unsigned)ecol < (unsigned)IMG) &&
                             ((unsigned)erow < (unsigned)IMG);

            #pragma unroll 2
            for (int i = 0; i < 4; i++) {
                const int c = cBase + i;
                const float* xc = xbase + ((size_t)i << 16);
                const float e = eok ? __ldg(xc + erow * IMG + ecol) : 0.f;

                float4 o0 = make_float4(0.f, 0.f, 0.f, 0.f);
                float4 o1 = make_float4(0.f, 0.f, 0.f, 0.f);
                float4 o2 = make_float4(0.f, 0.f, 0.f, 0.f);
                float4 o3 = make_float4(0.f, 0.f, 0.f, 0.f);

                #pragma unroll
                for (int k = 0; k < 6; k++) {
                    const int yk = y0 - 1 + k;
                    float4 v = ((unsigned)yk < (unsigned)IMG)
                             ? __ldg((const float4*)(xc + yk * IMG + x0) + lane)
                             : make_float4(0.f, 0.f, 0.f, 0.f);
                    float fL = __shfl_up_sync(0xffffffffu, v.w, 1);
                    const float eL = __shfl_sync(0xffffffffu, e, k);
                    if (lane == 0) fL = eL;
                    float fR = __shfl_down_sync(0xffffffffu, v.x, 1);
                    const float eR = __shfl_sync(0xffffffffu, e, 6 + k);
                    if (lane == 31) fR = eR;

                    // input row k contributes weight-row (k-j) to output j,
                    // for j in [max(0,k-2), min(3,k)]; j=k-2 completes.
                    #pragma unroll
                    for (int j = 0; j < 4; j++) {
                        if (k - j >= 0 && k - j <= 2) {
                            const int wr = k - j;
                            const float wa = c_dw[c * 9 + 3 * wr];
                            const float wb = c_dw[c * 9 + 3 * wr + 1];
                            const float wc = c_dw[c * 9 + 3 * wr + 2];
                            float4* o = (j == 0) ? &o0 : (j == 1) ? &o1
                                      : (j == 2) ? &o2 : &o3;
                            o->x = fmaf(wa, fL,  fmaf(wb, v.x, fmaf(wc, v.y, o->x)));
                            o->y = fmaf(wa, v.x, fmaf(wb, v.y, fmaf(wc, v.z, o->y)));
                            o->z = fmaf(wa, v.y, fmaf(wb, v.z, fmaf(wc, v.w, o->z)));
                            o->w = fmaf(wa, v.z, fmaf(wb, v.w, fmaf(wc, fR,  o->w)));
                        }
                    }
                    if (k >= 2) {   // output row k-2 complete -> store
                        const float4* o = (k == 2) ? &o0 : (k == 3) ? &o1
                                        : (k == 4) ? &o2 : &o3;
                        float4 st;
                        st.x = __uint_as_float(f2tf(o->x));
                        st.y = __uint_as_float(f2tf(o->y));
                        st.z = __uint_as_float(f2tf(o->z));
                        st.w = __uint_as_float(f2tf(o->w));
                        *reinterpret_cast<float4*>(
                            dws + c * DWS_S + (k - 2) * TW + 4 * lane) = st;
                    }
                }
            }
        }

        __syncthreads();   // dws ready

        // ---- channel mix: out[64,512] = M @ dw  via m16n8k8 tf32 MMA ----
        #pragma unroll
        for (int pair = 0; pair < 4; pair++) {
            const int pb0 = warpN * 64 + pair * 16;
            float acc[4][4] = {};   // [t0c0, t0c1, t1c0, t1c1]
            #pragma unroll
            for (int ks = 0; ks < 8; ks++) {
                const float* bp = dws + (ks * 8 + m) * DWS_S;
                unsigned b0a = __float_as_uint(bp[pb0 + g]);
                unsigned b1a = __float_as_uint(bp[4 * DWS_S + pb0 + g]);
                unsigned b0b = __float_as_uint(bp[pb0 + 8 + g]);
                unsigned b1b = __float_as_uint(bp[4 * DWS_S + pb0 + 8 + g]);
                mma_tf32(acc[0], afr[ks] + 0, b0a, b1a);
                mma_tf32(acc[1], afr[ks] + 0, b0b, b1b);
                mma_tf32(acc[2], afr[ks] + 4, b0a, b1a);
                mma_tf32(acc[3], afr[ks] + 4, b0b, b1b);
            }
            #pragma unroll
            for (int cc = 0; cc < 2; cc++) {
                const int p  = pb0 + 8 * cc + 2 * m;
                const int yy = y0 + (p >> 7);
                const int xx = x0 + (p & 127);
                #pragma unroll
                for (int tt = 0; tt < 2; tt++) {
                    const int och = warpM * 32 + g + 16 * tt;
                    const float* a = acc[2 * tt + cc];
                    size_t o1 = (((size_t)(b * NCH + och)) << 16) + yy * IMG + xx;
                    *reinterpret_cast<float2*>(out + o1) = make_float2(a[0], a[1]);
                    size_t o2 = (((size_t)(b * NCH + och + 8)) << 16) + yy * IMG + xx;
                    *reinterpret_cast<float2*>(out + o2) = make_float2(a[2], a[3]);
                }
            }
        }
    }
}

// ---------------------------------------------------------------------------
extern "C" void kernel_launch(void* const* d_in, const int* in_sizes, int n_in,
                              void* d_out, int out_size) {
    const float* x   = (const float*)d_in[0];   // [8,64,256,256]
    const float* dww = (const float*)d_in[1];   // [64,1,3,3]
    const float* pww = (const float*)d_in[2];   // [64,64,1,1]
    const float* aw  = (const float*)d_in[3];   // [64,64]
    const float* gw  = (const float*)d_in[4];   // [64,64]
    float* out = (float*)d_out;

    cudaMemcpyToSymbolAsync(c_dw, dww, NCH * 9 * sizeof(float), 0,
                            cudaMemcpyDeviceToDevice);
    kMall<<<16, 256>>>(aw, gw, pww);

    cudaFuncSetAttribute(fused_kernel,
                         cudaFuncAttributeMaxDynamicSharedMemorySize, SMEM_BYTES);
    fused_kernel<<<NCTA, 512, SMEM_BYTES>>>(x, out);
}